// round 13
// baseline (speedup 1.0000x reference)
#include <cuda_runtime.h>
#include <cuda_fp16.h>
#include <math.h>
#include <stdint.h>

#define NTOK   131072
#define NCODE  2048
#define DIM    64

// Output layout (tuple flattened):
#define OFF_XOUT   0
#define OFF_COMMIT 8388608
#define OFF_PERP   8388609
#define OFF_NCB    8388610
#define OFF_NSUM   8519682
#define OFF_NCNT   8650754

// ---- device scratch ----
__device__ float g_cnorm[NCODE];
__device__ float g_sumb[NCODE * DIM];
__device__ float g_cntb[NCODE];
__device__ float g_commit;
__device__ float g_plog;
__device__ __half g_ch[NCODE * DIM];
__device__ __half g_cm[NCODE * DIM];

__device__ __forceinline__ uint32_t smem_u32(const void* p) {
    uint32_t a;
    asm("{ .reg .u64 t; cvta.to.shared.u64 t, %1; cvt.u32.u64 %0, t; }" : "=r"(a) : "l"(p));
    return a;
}
#define LDX4(r, addr) \
    asm volatile("ldmatrix.sync.aligned.m8n8.x4.shared.b16 {%0,%1,%2,%3}, [%4];" \
        : "=r"((r)[0]), "=r"((r)[1]), "=r"((r)[2]), "=r"((r)[3]) : "r"(addr))

__device__ __forceinline__ void mma16816(float* c, const uint32_t* a, uint32_t b0, uint32_t b1) {
    asm volatile("mma.sync.aligned.m16n8k16.row.col.f32.f16.f16.f32 "
        "{%0,%1,%2,%3},{%4,%5,%6,%7},{%8,%9},{%0,%1,%2,%3};"
        : "+f"(c[0]), "+f"(c[1]), "+f"(c[2]), "+f"(c[3])
        : "r"(a[0]), "r"(a[1]), "r"(a[2]), "r"(a[3]), "r"(b0), "r"(b1));
}
__device__ __forceinline__ void cpa16(uint32_t dst, const void* src) {
    asm volatile("cp.async.cg.shared.global [%0], [%1], 16;" :: "r"(dst), "l"(src));
}
#define CPA_COMMIT() asm volatile("cp.async.commit_group;" ::: "memory")
#define CPA_WAIT1()  asm volatile("cp.async.wait_group 1;" ::: "memory")

union U8H { __half h[8]; uint4 u; };
union U4H { __half h[4]; uint2 u; };

// smem buffer layout (bytes): bh[128*144] @0, bm[128*144] @18432, cns[128]f @36864
#define BUFB   37376
#define OFF_BM 18432
#define OFF_CN 36864
#define OFF_XN (2 * BUFB)          // xns[128] floats, later reused as idx[128]
#define SMEMT  (2 * BUFB + 512)

// ---- K0: zero accumulators ----
__global__ void k_zero() {
    int i = blockIdx.x * 256 + threadIdx.x;
    if (i < NCODE * DIM) g_sumb[i] = 0.0f;
    if (i < NCODE)       g_cntb[i] = 0.0f;
    if (i == 0) { g_commit = 0.0f; g_plog = 0.0f; }
}

// ---- K0b: split codebook into fp16 pair + ||c||^2 (reference rounding) ----
__global__ void k_split_cb(const float* __restrict__ cb) {
    int c = blockIdx.x * 256 + threadIdx.x;
    if (c >= NCODE) return;
    const float4* cp = (const float4*)(cb + (size_t)c * DIM);
    float cn = 0.0f;
#pragma unroll
    for (int q = 0; q < 8; q++) {
        float4 a = cp[2 * q], b = cp[2 * q + 1];
        float v[8] = {a.x, a.y, a.z, a.w, b.x, b.y, b.z, b.w};
        U8H H, M;
#pragma unroll
        for (int i = 0; i < 8; i++) {
            float vi = v[i];
            __half hb = __float2half_rn(vi);
            __half mb = __float2half_rn(__fsub_rn(vi, __half2float(hb)));
            H.h[i] = hb; M.h[i] = mb;
            cn = __fadd_rn(cn, __fmul_rn(vi, vi));
        }
        *(uint4*)&g_ch[(size_t)c * DIM + q * 8] = H.u;
        *(uint4*)&g_cm[(size_t)c * DIM + q * 8] = M.u;
    }
    g_cnorm[c] = cn;
}

// ---- K1: HMMA fp16-split distance GEMM + filtered argmin + fused scatter ----
__device__ __forceinline__ void prefetch_chunk(uint32_t bsm, int n0, int tid) {
#pragma unroll
    for (int i = tid; i < 1024; i += 256) {
        int r = i >> 3, j = i & 7;
        cpa16(bsm + r * 144 + j * 16, &g_ch[(size_t)(n0 + r) * DIM + j * 8]);
        cpa16(bsm + OFF_BM + r * 144 + j * 16, &g_cm[(size_t)(n0 + r) * DIM + j * 8]);
    }
    if (tid < 32) cpa16(bsm + OFF_CN + tid * 16, &g_cnorm[n0 + tid * 4]);
}

__global__ void __launch_bounds__(256, 2) k1_hmma(const float* __restrict__ x,
                                                  const float* __restrict__ cb,
                                                  float* __restrict__ out) {
    extern __shared__ __align__(16) char dyn[];
    uint32_t sb = smem_u32(dyn);
    int tid = threadIdx.x, w = tid >> 5, l = tid & 31;
    int g = l >> 3, lr = l & 7, gid = l >> 2, tig = l & 3;
    int m0 = blockIdx.x * 128;
    float* xns = (float*)(dyn + OFF_XN);

    // in-kernel x split: fp32 -> (h, m) halves into buf0, ||x||^2 -> xns
    {
        int r = tid >> 1, seg = tid & 1;
        const float4* xp = (const float4*)(x + (size_t)(m0 + r) * DIM + seg * 32);
        float ps = 0.0f;
#pragma unroll
        for (int q = 0; q < 8; q++) {
            float4 v = xp[q];
            float vv[4] = {v.x, v.y, v.z, v.w};
            U4H H, M;
#pragma unroll
            for (int i = 0; i < 4; i++) {
                float vi = vv[i];
                __half hb = __float2half_rn(vi);
                __half mb = __float2half_rn(__fsub_rn(vi, __half2float(hb)));
                H.h[i] = hb; M.h[i] = mb;
                ps = __fadd_rn(ps, __fmul_rn(vi, vi));
            }
            int off = r * 144 + (seg * 32 + q * 4) * 2;
            *(uint2*)(dyn + off) = H.u;
            *(uint2*)(dyn + OFF_BM + off) = M.u;
        }
        float other = __shfl_xor_sync(0xffffffffu, ps, 1);
        float xnv = (seg == 0) ? __fadd_rn(ps, other) : __fadd_rn(other, ps);
        if (seg == 0) xns[r] = xnv;
    }
    __syncthreads();

    // A fragments register-resident for the whole kernel
    uint32_t ah[4][4], am[4][4];
    {
        int arow = w * 16 + (g & 1) * 8 + lr;
#pragma unroll
        for (int kk = 0; kk < 4; kk++) {
            int acol = kk * 16 + (g >> 1) * 8;
            LDX4(ah[kk], sb + arow * 144 + acol * 2);
            LDX4(am[kk], sb + OFF_BM + arow * 144 + acol * 2);
        }
    }
    float xn0 = xns[w * 16 + gid];
    float xn1 = xns[w * 16 + gid + 8];
    __syncthreads();

    float bv0 = 3.4e38f, bv1 = 3.4e38f;
    float thr0 = 3.4e38f, thr1 = 3.4e38f;
    int bi0 = 0, bi1 = 0;
    const float EPS = 1e-3f;

    prefetch_chunk(sb, 0, tid);          CPA_COMMIT();
    prefetch_chunk(sb + BUFB, 128, tid); CPA_COMMIT();

    for (int c = 0; c < 16; c++) {
        uint32_t bb = sb + (c & 1) * BUFB;
        const float* cns = (const float*)(dyn + (c & 1) * BUFB + OFF_CN);
        CPA_WAIT1();
        __syncthreads();

#pragma unroll
        for (int hf = 0; hf < 2; hf++) {
            float acc[8][4];
#pragma unroll
            for (int n = 0; n < 8; n++)
#pragma unroll
                for (int q = 0; q < 4; q++) acc[n][q] = 0.0f;

#pragma unroll
            for (int kk = 0; kk < 4; kk++) {
#pragma unroll
                for (int p = 0; p < 4; p++) {
                    int brow = hf * 64 + p * 16 + (g & 1) * 8 + lr;
                    int bcol = kk * 16 + (g >> 1) * 8;
                    uint32_t bh[4], bm[4];
                    LDX4(bh, bb + brow * 144 + bcol * 2);
                    LDX4(bm, bb + OFF_BM + brow * 144 + bcol * 2);
                    mma16816(acc[2 * p],     ah[kk], bh[0], bh[2]);
                    mma16816(acc[2 * p],     ah[kk], bm[0], bm[2]);
                    mma16816(acc[2 * p],     am[kk], bh[0], bh[2]);
                    mma16816(acc[2 * p + 1], ah[kk], bh[1], bh[3]);
                    mma16816(acc[2 * p + 1], ah[kk], bm[1], bm[3]);
                    mma16816(acc[2 * p + 1], am[kk], bh[1], bh[3]);
                }
            }
            // Filtered epilogue; skip provably safe, slow path exact reference order.
#pragma unroll
            for (int nt = 0; nt < 8; nt++) {
                int nl = hf * 64 + nt * 8 + 2 * tig;
                float cn0 = cns[nl], cn1 = cns[nl + 1];
                int ci = c * 128 + nl;
                float t0 = __fmaf_rn(-2.0f, acc[nt][0], cn0);
                float t1 = __fmaf_rn(-2.0f, acc[nt][1], cn1);
                float t2 = __fmaf_rn(-2.0f, acc[nt][2], cn0);
                float t3 = __fmaf_rn(-2.0f, acc[nt][3], cn1);
                bool p = (t0 < thr0) | (t1 < thr0) | (t2 < thr1) | (t3 < thr1);
                if (__any_sync(0xffffffffu, p)) {
                    float s;
                    s = __fadd_rn(__fsub_rn(xn0, __fmul_rn(2.0f, acc[nt][0])), cn0);
                    if (s < bv0) { bv0 = s; bi0 = ci; }
                    s = __fadd_rn(__fsub_rn(xn0, __fmul_rn(2.0f, acc[nt][1])), cn1);
                    if (s < bv0) { bv0 = s; bi0 = ci + 1; }
                    s = __fadd_rn(__fsub_rn(xn1, __fmul_rn(2.0f, acc[nt][2])), cn0);
                    if (s < bv1) { bv1 = s; bi1 = ci; }
                    s = __fadd_rn(__fsub_rn(xn1, __fmul_rn(2.0f, acc[nt][3])), cn1);
                    if (s < bv1) { bv1 = s; bi1 = ci + 1; }
                    thr0 = __fadd_rn(__fsub_rn(bv0, xn0), EPS);
                    thr1 = __fadd_rn(__fsub_rn(bv1, xn1), EPS);
                }
            }
        }
        __syncthreads();
        if (c + 2 < 16) prefetch_chunk(bb, (c + 2) * 128, tid);
        CPA_COMMIT();
    }

    // quad (4-lane) reduce, tie -> lower index
#pragma unroll
    for (int off = 1; off <= 2; off <<= 1) {
        float ov0 = __shfl_xor_sync(0xffffffffu, bv0, off);
        int   oi0 = __shfl_xor_sync(0xffffffffu, bi0, off);
        if (ov0 < bv0 || (ov0 == bv0 && oi0 < bi0)) { bv0 = ov0; bi0 = oi0; }
        float ov1 = __shfl_xor_sync(0xffffffffu, bv1, off);
        int   oi1 = __shfl_xor_sync(0xffffffffu, bi1, off);
        if (ov1 < bv1 || (ov1 == bv1 && oi1 < bi1)) { bv1 = ov1; bi1 = oi1; }
    }
    int* sidx = (int*)(dyn + OFF_XN);   // reuse xns region
    if (tig == 0) {
        sidx[w * 16 + gid]     = bi0;
        sidx[w * 16 + gid + 8] = bi1;
    }
    __syncthreads();

    // ---- fused scatter: 2 threads per token, 32 dims each ----
    {
        int t = tid >> 1, seg = tid & 1;
        int gt = m0 + t;
        int idx = sidx[t];
        const float4* xp = (const float4*)(x + (size_t)gt * DIM + seg * 32);
        const float4* cp = (const float4*)(cb + (size_t)idx * DIM + seg * 32);
        float4* op = (float4*)(out + OFF_XOUT + (size_t)gt * DIM + seg * 32);
        float* sbm = &g_sumb[idx * DIM + seg * 32];
        float cs = 0.0f;
#pragma unroll
        for (int q = 0; q < 8; q++) {
            float4 xv = xp[q];
            float4 cv = cp[q];
            float4 o;
            o.x = __fadd_rn(xv.x, __fsub_rn(cv.x, xv.x));
            o.y = __fadd_rn(xv.y, __fsub_rn(cv.y, xv.y));
            o.z = __fadd_rn(xv.z, __fsub_rn(cv.z, xv.z));
            o.w = __fadd_rn(xv.w, __fsub_rn(cv.w, xv.w));
            op[q] = o;
            float dx = __fsub_rn(xv.x, cv.x), dy = __fsub_rn(xv.y, cv.y);
            float dz = __fsub_rn(xv.z, cv.z), dw = __fsub_rn(xv.w, cv.w);
            cs += dx * dx + dy * dy + dz * dz + dw * dw;
            atomicAdd(sbm + q * 4 + 0, xv.x);
            atomicAdd(sbm + q * 4 + 1, xv.y);
            atomicAdd(sbm + q * 4 + 2, xv.z);
            atomicAdd(sbm + q * 4 + 3, xv.w);
        }
        if (seg == 0) atomicAdd(&g_cntb[idx], 1.0f);
#pragma unroll
        for (int o = 16; o; o >>= 1) cs += __shfl_xor_sync(0xffffffffu, cs, o);
        if (l == 0) atomicAdd(&g_commit, cs);
    }
}

// ---- K3: EMA update, new codebook, perplexity partials ----
__global__ void k_final(const float* __restrict__ x, const float* __restrict__ code_sum,
                        const float* __restrict__ code_count, float* __restrict__ out) {
    int i = blockIdx.x * 256 + threadIdx.x;
    int c = i >> 6, d = i & 63;
    float cntb = g_cntb[c];
    float ncnt = 0.99f * code_count[c] + 0.01f * cntb;
    float ns = 0.99f * code_sum[i] + 0.01f * g_sumb[i];
    out[OFF_NSUM + i] = ns;
    bool used = (ncnt >= 1.0f);
    float refreshed = ns / fmaxf(ncnt, 1e-8f);
    out[OFF_NCB + i] = used ? refreshed : x[i];
    if (d == 0) {
        out[OFF_NCNT + c] = ncnt;
        float p = cntb * (1.0f / 131072.0f);
        atomicAdd(&g_plog, p * logf(p + 1e-7f));
    }
}

// ---- K4: scalars ----
__global__ void k_scalars(float* __restrict__ out) {
    out[OFF_COMMIT] = g_commit * (1.0f / 8388608.0f);
    out[OFF_PERP]   = expf(-g_plog);
}

extern "C" void kernel_launch(void* const* d_in, const int* in_sizes, int n_in,
                              void* d_out, int out_size) {
    const float* x    = (const float*)d_in[0];
    const float* cb   = (const float*)d_in[1];
    const float* csum = (const float*)d_in[2];
    const float* ccnt = (const float*)d_in[3];
    float* out = (float*)d_out;

    cudaFuncSetAttribute(k1_hmma, cudaFuncAttributeMaxDynamicSharedMemorySize, SMEMT);

    k_zero<<<512, 256>>>();
    k_split_cb<<<8, 256>>>(cb);
    k1_hmma<<<NTOK / 128, 256, SMEMT>>>(x, cb, out);
    k_final<<<NCODE * DIM / 256, 256>>>(x, csum, ccnt, out);
    k_scalars<<<1, 1>>>(out);
}

// round 14
// speedup vs baseline: 1.0704x; 1.0704x over previous
#include <cuda_runtime.h>
#include <cuda_fp16.h>
#include <math.h>
#include <stdint.h>

#define NTOK   131072
#define NCODE  2048
#define DIM    64

// Output layout (tuple flattened):
#define OFF_XOUT   0
#define OFF_COMMIT 8388608
#define OFF_PERP   8388609
#define OFF_NCB    8388610
#define OFF_NSUM   8519682
#define OFF_NCNT   8650754

// ---- device scratch ----
__device__ int   g_idx[NTOK];
__device__ int   g_hist[NCODE];
__device__ int   g_start[NCODE];
__device__ int   g_cursor[NCODE];
__device__ int   g_tok[NTOK];
__device__ float g_cnorm[NCODE];
__device__ float g_sumb[NCODE * DIM];
__device__ float g_commit;
__device__ float g_plog;
__device__ __half g_ch[NCODE * DIM];
__device__ __half g_cm[NCODE * DIM];

__device__ __forceinline__ uint32_t smem_u32(const void* p) {
    uint32_t a;
    asm("{ .reg .u64 t; cvta.to.shared.u64 t, %1; cvt.u32.u64 %0, t; }" : "=r"(a) : "l"(p));
    return a;
}
#define LDX4(r, addr) \
    asm volatile("ldmatrix.sync.aligned.m8n8.x4.shared.b16 {%0,%1,%2,%3}, [%4];" \
        : "=r"((r)[0]), "=r"((r)[1]), "=r"((r)[2]), "=r"((r)[3]) : "r"(addr))

__device__ __forceinline__ void mma16816(float* c, const uint32_t* a, uint32_t b0, uint32_t b1) {
    asm volatile("mma.sync.aligned.m16n8k16.row.col.f32.f16.f16.f32 "
        "{%0,%1,%2,%3},{%4,%5,%6,%7},{%8,%9},{%0,%1,%2,%3};"
        : "+f"(c[0]), "+f"(c[1]), "+f"(c[2]), "+f"(c[3])
        : "r"(a[0]), "r"(a[1]), "r"(a[2]), "r"(a[3]), "r"(b0), "r"(b1));
}
__device__ __forceinline__ void cpa16(uint32_t dst, const void* src) {
    asm volatile("cp.async.cg.shared.global [%0], [%1], 16;" :: "r"(dst), "l"(src));
}
#define CPA_COMMIT() asm volatile("cp.async.commit_group;" ::: "memory")
#define CPA_WAIT1()  asm volatile("cp.async.wait_group 1;" ::: "memory")

union U8H { __half h[8]; uint4 u; };
union U4H { __half h[4]; uint2 u; };

#define BUFB   37376
#define OFF_BM 18432
#define OFF_CN 36864
#define OFF_XN (2 * BUFB)
#define SMEMT  (2 * BUFB + 512)

// ---- K0: zero scalars + histogram ----
__global__ void k_zero() {
    int i = blockIdx.x * 256 + threadIdx.x;
    if (i < NCODE) g_hist[i] = 0;
    if (i == 0) { g_commit = 0.0f; g_plog = 0.0f; }
}

// ---- K0b: split codebook into fp16 pair + ||c||^2 (reference rounding) ----
__global__ void k_split_cb(const float* __restrict__ cb) {
    int c = blockIdx.x * 256 + threadIdx.x;
    if (c >= NCODE) return;
    const float4* cp = (const float4*)(cb + (size_t)c * DIM);
    float cn = 0.0f;
#pragma unroll
    for (int q = 0; q < 8; q++) {
        float4 a = cp[2 * q], b = cp[2 * q + 1];
        float v[8] = {a.x, a.y, a.z, a.w, b.x, b.y, b.z, b.w};
        U8H H, M;
#pragma unroll
        for (int i = 0; i < 8; i++) {
            float vi = v[i];
            __half hb = __float2half_rn(vi);
            __half mb = __float2half_rn(__fsub_rn(vi, __half2float(hb)));
            H.h[i] = hb; M.h[i] = mb;
            cn = __fadd_rn(cn, __fmul_rn(vi, vi));
        }
        *(uint4*)&g_ch[(size_t)c * DIM + q * 8] = H.u;
        *(uint4*)&g_cm[(size_t)c * DIM + q * 8] = M.u;
    }
    g_cnorm[c] = cn;
}

// ---- K1: HMMA fp16-split distance GEMM + filtered fused argmin ----
__device__ __forceinline__ void prefetch_chunk(uint32_t bsm, int n0, int tid) {
#pragma unroll
    for (int i = tid; i < 1024; i += 256) {
        int r = i >> 3, j = i & 7;
        cpa16(bsm + r * 144 + j * 16, &g_ch[(size_t)(n0 + r) * DIM + j * 8]);
        cpa16(bsm + OFF_BM + r * 144 + j * 16, &g_cm[(size_t)(n0 + r) * DIM + j * 8]);
    }
    if (tid < 32) cpa16(bsm + OFF_CN + tid * 16, &g_cnorm[n0 + tid * 4]);
}

__global__ void __launch_bounds__(256, 2) k1_hmma(const float* __restrict__ x) {
    extern __shared__ __align__(16) char dyn[];
    uint32_t sb = smem_u32(dyn);
    int tid = threadIdx.x, w = tid >> 5, l = tid & 31;
    int g = l >> 3, lr = l & 7, gid = l >> 2, tig = l & 3;
    int m0 = blockIdx.x * 128;
    float* xns = (float*)(dyn + OFF_XN);

    // in-kernel x split: fp32 -> (h, m) halves into buf0, ||x||^2 -> xns
    {
        int r = tid >> 1, seg = tid & 1;
        const float4* xp = (const float4*)(x + (size_t)(m0 + r) * DIM + seg * 32);
        float ps = 0.0f;
#pragma unroll
        for (int q = 0; q < 8; q++) {
            float4 v = xp[q];
            float vv[4] = {v.x, v.y, v.z, v.w};
            U4H H, M;
#pragma unroll
            for (int i = 0; i < 4; i++) {
                float vi = vv[i];
                __half hb = __float2half_rn(vi);
                __half mb = __float2half_rn(__fsub_rn(vi, __half2float(hb)));
                H.h[i] = hb; M.h[i] = mb;
                ps = __fadd_rn(ps, __fmul_rn(vi, vi));
            }
            int off = r * 144 + (seg * 32 + q * 4) * 2;
            *(uint2*)(dyn + off) = H.u;
            *(uint2*)(dyn + OFF_BM + off) = M.u;
        }
        float other = __shfl_xor_sync(0xffffffffu, ps, 1);
        float xnv = (seg == 0) ? __fadd_rn(ps, other) : __fadd_rn(other, ps);
        if (seg == 0) xns[r] = xnv;
    }
    __syncthreads();

    uint32_t ah[4][4], am[4][4];
    {
        int arow = w * 16 + (g & 1) * 8 + lr;
#pragma unroll
        for (int kk = 0; kk < 4; kk++) {
            int acol = kk * 16 + (g >> 1) * 8;
            LDX4(ah[kk], sb + arow * 144 + acol * 2);
            LDX4(am[kk], sb + OFF_BM + arow * 144 + acol * 2);
        }
    }
    float xn0 = xns[w * 16 + gid];
    float xn1 = xns[w * 16 + gid + 8];
    __syncthreads();

    float bv0 = 3.4e38f, bv1 = 3.4e38f;
    float thr0 = 3.4e38f, thr1 = 3.4e38f;
    int bi0 = 0, bi1 = 0;
    const float EPS = 1e-3f;

    prefetch_chunk(sb, 0, tid);          CPA_COMMIT();
    prefetch_chunk(sb + BUFB, 128, tid); CPA_COMMIT();

    for (int c = 0; c < 16; c++) {
        uint32_t bb = sb + (c & 1) * BUFB;
        const float* cns = (const float*)(dyn + (c & 1) * BUFB + OFF_CN);
        CPA_WAIT1();
        __syncthreads();

#pragma unroll
        for (int hf = 0; hf < 2; hf++) {
            float acc[8][4];
#pragma unroll
            for (int n = 0; n < 8; n++)
#pragma unroll
                for (int q = 0; q < 4; q++) acc[n][q] = 0.0f;

#pragma unroll
            for (int kk = 0; kk < 4; kk++) {
#pragma unroll
                for (int p = 0; p < 4; p++) {
                    int brow = hf * 64 + p * 16 + (g & 1) * 8 + lr;
                    int bcol = kk * 16 + (g >> 1) * 8;
                    uint32_t bh[4], bm[4];
                    LDX4(bh, bb + brow * 144 + bcol * 2);
                    LDX4(bm, bb + OFF_BM + brow * 144 + bcol * 2);
                    mma16816(acc[2 * p],     ah[kk], bh[0], bh[2]);
                    mma16816(acc[2 * p],     ah[kk], bm[0], bm[2]);
                    mma16816(acc[2 * p],     am[kk], bh[0], bh[2]);
                    mma16816(acc[2 * p + 1], ah[kk], bh[1], bh[3]);
                    mma16816(acc[2 * p + 1], ah[kk], bm[1], bm[3]);
                    mma16816(acc[2 * p + 1], am[kk], bh[1], bh[3]);
                }
            }
            // Filtered epilogue; skip provably safe, slow path exact reference order.
#pragma unroll
            for (int nt = 0; nt < 8; nt++) {
                int nl = hf * 64 + nt * 8 + 2 * tig;
                float cn0 = cns[nl], cn1 = cns[nl + 1];
                int ci = c * 128 + nl;
                float t0 = __fmaf_rn(-2.0f, acc[nt][0], cn0);
                float t1 = __fmaf_rn(-2.0f, acc[nt][1], cn1);
                float t2 = __fmaf_rn(-2.0f, acc[nt][2], cn0);
                float t3 = __fmaf_rn(-2.0f, acc[nt][3], cn1);
                bool p = (t0 < thr0) | (t1 < thr0) | (t2 < thr1) | (t3 < thr1);
                if (__any_sync(0xffffffffu, p)) {
                    float s;
                    s = __fadd_rn(__fsub_rn(xn0, __fmul_rn(2.0f, acc[nt][0])), cn0);
                    if (s < bv0) { bv0 = s; bi0 = ci; }
                    s = __fadd_rn(__fsub_rn(xn0, __fmul_rn(2.0f, acc[nt][1])), cn1);
                    if (s < bv0) { bv0 = s; bi0 = ci + 1; }
                    s = __fadd_rn(__fsub_rn(xn1, __fmul_rn(2.0f, acc[nt][2])), cn0);
                    if (s < bv1) { bv1 = s; bi1 = ci; }
                    s = __fadd_rn(__fsub_rn(xn1, __fmul_rn(2.0f, acc[nt][3])), cn1);
                    if (s < bv1) { bv1 = s; bi1 = ci + 1; }
                    thr0 = __fadd_rn(__fsub_rn(bv0, xn0), EPS);
                    thr1 = __fadd_rn(__fsub_rn(bv1, xn1), EPS);
                }
            }
        }
        __syncthreads();
        if (c + 2 < 16) prefetch_chunk(bb, (c + 2) * 128, tid);
        CPA_COMMIT();
    }

#pragma unroll
    for (int off = 1; off <= 2; off <<= 1) {
        float ov0 = __shfl_xor_sync(0xffffffffu, bv0, off);
        int   oi0 = __shfl_xor_sync(0xffffffffu, bi0, off);
        if (ov0 < bv0 || (ov0 == bv0 && oi0 < bi0)) { bv0 = ov0; bi0 = oi0; }
        float ov1 = __shfl_xor_sync(0xffffffffu, bv1, off);
        int   oi1 = __shfl_xor_sync(0xffffffffu, bi1, off);
        if (ov1 < bv1 || (ov1 == bv1 && oi1 < bi1)) { bv1 = ov1; bi1 = oi1; }
    }
    if (tig == 0) {
        g_idx[m0 + w * 16 + gid]     = bi0;
        g_idx[m0 + w * 16 + gid + 8] = bi1;
    }
}

// ---- K2a: histogram of code usage ----
__global__ void k_hist() {
    int t = blockIdx.x * 256 + threadIdx.x;
    atomicAdd(&g_hist[g_idx[t]], 1);
}

// ---- K2b: exclusive prefix scan over 2048 counts (1 block, 256 threads) ----
__global__ void k_prefix() {
    __shared__ int warpsum[8];
    int tid = threadIdx.x, lane = tid & 31, wid = tid >> 5;
    int loc[8], s = 0;
#pragma unroll
    for (int j = 0; j < 8; j++) { loc[j] = s; s += g_hist[tid * 8 + j]; }
    int v = s;
#pragma unroll
    for (int off = 1; off < 32; off <<= 1) {
        int t = __shfl_up_sync(0xffffffffu, v, off);
        if (lane >= off) v += t;
    }
    if (lane == 31) warpsum[wid] = v;
    __syncthreads();
    if (wid == 0) {
        int wv = (lane < 8) ? warpsum[lane] : 0;
#pragma unroll
        for (int off = 1; off < 8; off <<= 1) {
            int t = __shfl_up_sync(0xffffffffu, wv, off);
            if (lane >= off) wv += t;
        }
        if (lane < 8) warpsum[lane] = wv;
    }
    __syncthreads();
    int base = ((wid > 0) ? warpsum[wid - 1] : 0) + (v - s);
#pragma unroll
    for (int j = 0; j < 8; j++) {
        g_start[tid * 8 + j]  = base + loc[j];
        g_cursor[tid * 8 + j] = base + loc[j];
    }
}

// ---- K2c: place tokens into sorted-by-code order ----
__global__ void k_place() {
    int t = blockIdx.x * 256 + threadIdx.x;
    int pos = atomicAdd(&g_cursor[g_idx[t]], 1);
    g_tok[pos] = t;
}

// ---- K2d: per-code gather-sum (1 warp per code): code_sum_batch, x_out, commit ----
__global__ void k_sum(const float* __restrict__ x, const float* __restrict__ cb,
                      float* __restrict__ out) {
    int wid = threadIdx.x >> 5, l = threadIdx.x & 31;
    int c = blockIdx.x * 8 + wid;
    int d0 = l * 2;
    float cv0 = cb[(size_t)c * DIM + d0], cv1 = cb[(size_t)c * DIM + d0 + 1];
    int beg = g_start[c], n = g_hist[c];
    float s0 = 0.0f, s1 = 0.0f, cs = 0.0f;
    for (int i = 0; i < n; i++) {
        int t = g_tok[beg + i];
        float2 xv = *(const float2*)(x + (size_t)t * DIM + d0);
        float2 o;
        o.x = __fadd_rn(xv.x, __fsub_rn(cv0, xv.x));
        o.y = __fadd_rn(xv.y, __fsub_rn(cv1, xv.y));
        *(float2*)(out + OFF_XOUT + (size_t)t * DIM + d0) = o;
        s0 += xv.x; s1 += xv.y;
        float dx = __fsub_rn(xv.x, cv0), dy = __fsub_rn(xv.y, cv1);
        cs += dx * dx + dy * dy;
    }
    g_sumb[(size_t)c * DIM + d0]     = s0;
    g_sumb[(size_t)c * DIM + d0 + 1] = s1;
#pragma unroll
    for (int o = 16; o; o >>= 1) cs += __shfl_xor_sync(0xffffffffu, cs, o);
    if (l == 0) atomicAdd(&g_commit, cs);
}

// ---- K3: EMA update, new codebook, perplexity partials ----
__global__ void k_final(const float* __restrict__ x, const float* __restrict__ code_sum,
                        const float* __restrict__ code_count, float* __restrict__ out) {
    int i = blockIdx.x * 256 + threadIdx.x;
    int c = i >> 6, d = i & 63;
    float cntb = (float)g_hist[c];
    float ncnt = 0.99f * code_count[c] + 0.01f * cntb;
    float ns = 0.99f * code_sum[i] + 0.01f * g_sumb[i];
    out[OFF_NSUM + i] = ns;
    bool used = (ncnt >= 1.0f);
    float refreshed = ns / fmaxf(ncnt, 1e-8f);
    out[OFF_NCB + i] = used ? refreshed : x[i];
    if (d == 0) {
        out[OFF_NCNT + c] = ncnt;
        float p = cntb * (1.0f / 131072.0f);
        atomicAdd(&g_plog, p * logf(p + 1e-7f));
    }
}

// ---- K4: scalars ----
__global__ void k_scalars(float* __restrict__ out) {
    out[OFF_COMMIT] = g_commit * (1.0f / 8388608.0f);
    out[OFF_PERP]   = expf(-g_plog);
}

extern "C" void kernel_launch(void* const* d_in, const int* in_sizes, int n_in,
                              void* d_out, int out_size) {
    const float* x    = (const float*)d_in[0];
    const float* cb   = (const float*)d_in[1];
    const float* csum = (const float*)d_in[2];
    const float* ccnt = (const float*)d_in[3];
    float* out = (float*)d_out;

    cudaFuncSetAttribute(k1_hmma, cudaFuncAttributeMaxDynamicSharedMemorySize, SMEMT);

    k_zero<<<8, 256>>>();
    k_split_cb<<<8, 256>>>(cb);
    k1_hmma<<<NTOK / 128, 256, SMEMT>>>(x);
    k_hist<<<NTOK / 256, 256>>>();
    k_prefix<<<1, 256>>>();
    k_place<<<NTOK / 256, 256>>>();
    k_sum<<<NCODE / 8, 256>>>(x, cb, out);
    k_final<<<NCODE * DIM / 256, 256>>>(x, csum, ccnt, out);
    k_scalars<<<1, 1>>>(out);
}